// round 1
// baseline (speedup 1.0000x reference)
#include <cuda_runtime.h>
#include <math.h>

// coeff[e] = (q0,q1,q2,q3) coefficients of the 81-term multilinear expansion
__device__ float4 g_coeff[81];

// ---------------------------------------------------------------------------
// Prep kernel: from theta (6 floats), build U (16x16 complex), A_q = Re(U^H Z_q U),
// then collapse to the 81-term coefficient tensor. One block, 256 threads, ~runs in <2us.
// ---------------------------------------------------------------------------

__device__ __forceinline__ void apply1q(float* vr, float* vi, int w,
    float g00r, float g00i, float g01r, float g01i,
    float g10r, float g10i, float g11r, float g11i)
{
    int m = 8 >> w;   // wire w lives at bit (3-w)
    #pragma unroll
    for (int z = 0; z < 16; z++) {
        if (z & m) continue;
        int z1 = z | m;
        float ar = vr[z],  ai = vi[z];
        float br = vr[z1], bi = vi[z1];
        vr[z]  = g00r*ar - g00i*ai + g01r*br - g01i*bi;
        vi[z]  = g00r*ai + g00i*ar + g01r*bi + g01i*br;
        vr[z1] = g10r*ar - g10i*ai + g11r*br - g11i*bi;
        vi[z1] = g10r*ai + g10i*ar + g11r*bi + g11i*br;
    }
}

__device__ __forceinline__ void applycnot(float* vr, float* vi, int c, int tg)
{
    int mc = 8 >> c, mt = 8 >> tg;
    #pragma unroll
    for (int z = 0; z < 16; z++) {
        if ((z & mc) && !(z & mt)) {
            int z1 = z | mt;
            float tr = vr[z], ti = vi[z];
            vr[z] = vr[z1]; vi[z] = vi[z1];
            vr[z1] = tr;    vi[z1] = ti;
        }
    }
}

__global__ void prep_kernel(const float* __restrict__ theta)
{
    __shared__ float Ur[16][16];   // Ur[z][col]
    __shared__ float Ui[16][16];
    __shared__ float A[4][16][16];
    int t = threadIdx.x;

    if (t < 16) {
        float vr[16], vi[16];
        #pragma unroll
        for (int z = 0; z < 16; z++) { vr[z] = 0.f; vi[z] = 0.f; }
        vr[t] = 1.f;

        float th0 = theta[0], th1 = theta[1], th2 = theta[2];
        float th3 = theta[3], th4 = theta[4], th5 = theta[5];

        // Ry(th0) wire 0
        { float c = cosf(0.5f*th0), s = sinf(0.5f*th0);
          apply1q(vr, vi, 0,  c,0.f, -s,0.f,  s,0.f,  c,0.f); }
        // Rx(th1) wire 1
        { float c = cosf(0.5f*th1), s = sinf(0.5f*th1);
          apply1q(vr, vi, 1,  c,0.f, 0.f,-s, 0.f,-s,  c,0.f); }
        // Rz(th2) wire 2
        { float c = cosf(0.5f*th2), s = sinf(0.5f*th2);
          apply1q(vr, vi, 2,  c,-s, 0.f,0.f, 0.f,0.f,  c,s); }
        // CNOT(0,1)
        applycnot(vr, vi, 0, 1);
        // Ry(th3) wire 3
        { float c = cosf(0.5f*th3), s = sinf(0.5f*th3);
          apply1q(vr, vi, 3,  c,0.f, -s,0.f,  s,0.f,  c,0.f); }
        // CNOT(2,3)
        applycnot(vr, vi, 2, 3);
        // Rx(th4) wire 0
        { float c = cosf(0.5f*th4), s = sinf(0.5f*th4);
          apply1q(vr, vi, 0,  c,0.f, 0.f,-s, 0.f,-s,  c,0.f); }
        // Rz(th5) wire 3
        { float c = cosf(0.5f*th5), s = sinf(0.5f*th5);
          apply1q(vr, vi, 3,  c,-s, 0.f,0.f, 0.f,0.f,  c,s); }

        #pragma unroll
        for (int z = 0; z < 16; z++) { Ur[z][t] = vr[z]; Ui[z][t] = vi[z]; }
    }
    __syncthreads();

    // A_q[i][j] = sum_z sign_q(z) * Re(conj(U[z][i]) * U[z][j])
    {
        int i = t >> 4, j = t & 15;   // t in 0..255
        float a0 = 0.f, a1 = 0.f, a2 = 0.f, a3 = 0.f;
        #pragma unroll
        for (int z = 0; z < 16; z++) {
            float re = Ur[z][i]*Ur[z][j] + Ui[z][i]*Ui[z][j];
            a0 += ((z >> 3) & 1) ? -re : re;
            a1 += ((z >> 2) & 1) ? -re : re;
            a2 += ((z >> 1) & 1) ? -re : re;
            a3 += ( z       & 1) ? -re : re;
        }
        A[0][i][j] = a0; A[1][i][j] = a1; A[2][i][j] = a2; A[3][i][j] = a3;
    }
    __syncthreads();

    // coeff_q[e0,e1,e2,e3] = (1/16) * sum over 16 pair-selections of +-A_q[i][j]
    if (t < 81) {
        int e = t;
        int ew[4];
        ew[0] = e / 27; ew[1] = (e / 9) % 3; ew[2] = (e / 3) % 3; ew[3] = e % 3;
        float c0 = 0.f, c1 = 0.f, c2 = 0.f, c3 = 0.f;
        for (int s = 0; s < 16; s++) {
            int i = 0, j = 0; float sg = 1.f;
            #pragma unroll
            for (int w = 0; w < 4; w++) {
                int bsel = (s >> w) & 1;
                int iw, jw; float ss;
                if (ew[w] == 0)      { iw = bsel; jw = bsel;     ss = 1.f; }
                else if (ew[w] == 1) { iw = bsel; jw = bsel;     ss = bsel ? -1.f : 1.f; }
                else                 { iw = bsel; jw = 1 - bsel; ss = 1.f; }
                i |= iw << (3 - w);
                j |= jw << (3 - w);
                sg *= ss;
            }
            c0 += sg * A[0][i][j];
            c1 += sg * A[1][i][j];
            c2 += sg * A[2][i][j];
            c3 += sg * A[3][i][j];
        }
        g_coeff[e] = make_float4(0.0625f*c0, 0.0625f*c1, 0.0625f*c2, 0.0625f*c3);
    }
}

// ---------------------------------------------------------------------------
// Main fused kernel: one block per image.
//   Phase 1 (196 threads): conv 2x2/s2 -> 4 angles -> 81-term quantum features
//   Phase 2 (256 threads): 784x10 GEMV + log_softmax
// ---------------------------------------------------------------------------

__global__ __launch_bounds__(256, 8)
void quanv_kernel(const float* __restrict__ x,
                  const float* __restrict__ cw,
                  const float* __restrict__ W,
                  const float* __restrict__ bvec,
                  float* __restrict__ out)
{
    __shared__ float4 sc[81];
    __shared__ __align__(16) float feats[784];
    __shared__ float wpart[8][10];
    __shared__ float slog[10];

    int t = threadIdx.x;
    int b = blockIdx.x;

    if (t < 81) sc[t] = g_coeff[t];
    float w00 = cw[0], w01 = cw[1], w10 = cw[2], w11 = cw[3];
    __syncthreads();

    if (t < 196) {
        int r  = t / 7;       // conv-output row 0..27
        int c4 = t % 7;       // patch-col group 0..6
        const float* px = x + (size_t)b * 3136 + (2*r) * 56 + 8 * c4;
        float4 r0a = *(const float4*)(px);
        float4 r0b = *(const float4*)(px + 4);
        float4 r1a = *(const float4*)(px + 56);
        float4 r1b = *(const float4*)(px + 60);

        float d0 = w00*r0a.x + w01*r0a.y + w10*r1a.x + w11*r1a.y;
        float d1 = w00*r0a.z + w01*r0a.w + w10*r1a.z + w11*r1a.w;
        float d2 = w00*r0b.x + w01*r0b.y + w10*r1b.x + w11*r1b.y;
        float d3 = w00*r0b.z + w01*r0b.w + w10*r1b.z + w11*r1b.w;

        float s0, c0, s1, c1, s2, c2, s3, c3;
        __sincosf(d0, &s0, &c0);
        __sincosf(d1, &s1, &c1);
        __sincosf(d2, &s2, &c2);
        __sincosf(d3, &s3, &c3);

        float f0[3] = {1.f, c0, s0};
        float f1[3] = {1.f, c1, s1};
        float f2[3] = {1.f, c2, s2};
        float f3[3] = {1.f, c3, s3};

        float m0 = 0.f, m1 = 0.f, m2 = 0.f, m3 = 0.f;
        int idx = 0;
        #pragma unroll
        for (int e0 = 0; e0 < 3; e0++) {
            float pa = f0[e0];
            #pragma unroll
            for (int e1 = 0; e1 < 3; e1++) {
                float pb = pa * f1[e1];
                #pragma unroll
                for (int e2 = 0; e2 < 3; e2++) {
                    float pc = pb * f2[e2];
                    #pragma unroll
                    for (int e3 = 0; e3 < 3; e3++) {
                        float pd = pc * f3[e3];
                        float4 k = sc[idx++];
                        m0 = fmaf(k.x, pd, m0);
                        m1 = fmaf(k.y, pd, m1);
                        m2 = fmaf(k.z, pd, m2);
                        m3 = fmaf(k.w, pd, m3);
                    }
                }
            }
        }
        *(float4*)(&feats[4 * t]) = make_float4(m0, m1, m2, m3);
    }
    __syncthreads();

    // GEMV: logits[k] = b[k] + sum_f feats[f] * W[k*784+f]
    float acc[10];
    #pragma unroll
    for (int k = 0; k < 10; k++) acc[k] = 0.f;
    for (int f = t; f < 784; f += 256) {
        float v = feats[f];
        #pragma unroll
        for (int k = 0; k < 10; k++)
            acc[k] = fmaf(v, __ldg(&W[k * 784 + f]), acc[k]);
    }
    #pragma unroll
    for (int k = 0; k < 10; k++) {
        float v = acc[k];
        v += __shfl_xor_sync(0xffffffffu, v, 16);
        v += __shfl_xor_sync(0xffffffffu, v, 8);
        v += __shfl_xor_sync(0xffffffffu, v, 4);
        v += __shfl_xor_sync(0xffffffffu, v, 2);
        v += __shfl_xor_sync(0xffffffffu, v, 1);
        acc[k] = v;
    }
    int lane = t & 31, wid = t >> 5;
    if (lane == 0) {
        #pragma unroll
        for (int k = 0; k < 10; k++) wpart[wid][k] = acc[k];
    }
    __syncthreads();
    if (t < 10) {
        float v = bvec[t];
        #pragma unroll
        for (int w = 0; w < 8; w++) v += wpart[w][t];
        slog[t] = v;
    }
    __syncthreads();
    if (t == 0) {
        float mx = slog[0];
        #pragma unroll
        for (int k = 1; k < 10; k++) mx = fmaxf(mx, slog[k]);
        float se = 0.f;
        #pragma unroll
        for (int k = 0; k < 10; k++) se += __expf(slog[k] - mx);
        float l = mx + __logf(se);
        #pragma unroll
        for (int k = 0; k < 10; k++) out[(size_t)b * 10 + k] = slog[k] - l;
    }
}

// ---------------------------------------------------------------------------

extern "C" void kernel_launch(void* const* d_in, const int* in_sizes, int n_in,
                              void* d_out, int out_size)
{
    const float* x     = (const float*)d_in[0];   // [2048,1,56,56]
    const float* cw    = (const float*)d_in[1];   // [1,1,2,2]
    const float* theta = (const float*)d_in[2];   // [6]
    const float* W     = (const float*)d_in[3];   // [10,784]
    const float* bvec  = (const float*)d_in[4];   // [10]
    float* out = (float*)d_out;                   // [2048,10]

    int B = in_sizes[0] / 3136;                   // 2048

    prep_kernel<<<1, 256>>>(theta);
    quanv_kernel<<<B, 256>>>(x, cw, W, bvec, out);
}

// round 2
// speedup vs baseline: 1.0932x; 1.0932x over previous
#include <cuda_runtime.h>
#include <math.h>

// Duplicated-coefficient table: g_cd[e][2q], g_cd[e][2q+1] = coeff_q[e]
// (pre-duplicated so packed f32x2 FMA needs no per-term register packing)
__device__ __align__(16) float g_cd[81][8];

// ---------------------------------------------------------------------------
// Packed fp32x2 helpers (Blackwell sm_100+)
// ---------------------------------------------------------------------------
typedef unsigned long long F2;

__device__ __forceinline__ F2 mul2(F2 a, F2 b) {
    F2 d; asm("mul.rn.f32x2 %0, %1, %2;" : "=l"(d) : "l"(a), "l"(b)); return d;
}
__device__ __forceinline__ F2 fma2(F2 a, F2 b, F2 c) {
    F2 d; asm("fma.rn.f32x2 %0, %1, %2, %3;" : "=l"(d) : "l"(a), "l"(b), "l"(c)); return d;
}
__device__ __forceinline__ F2 pack2(float lo, float hi) {
    F2 d;
    asm("mov.b64 %0, {%1, %2};" : "=l"(d) : "r"(__float_as_uint(lo)), "r"(__float_as_uint(hi)));
    return d;
}
__device__ __forceinline__ void unpack2(F2 v, float& lo, float& hi) {
    unsigned int a, b;
    asm("mov.b64 {%0, %1}, %2;" : "=r"(a), "=r"(b) : "l"(v));
    lo = __uint_as_float(a); hi = __uint_as_float(b);
}

// ---------------------------------------------------------------------------
// Prep kernel: from theta (6 floats), build U (16x16 complex), A_q = Re(U^H Z_q U),
// collapse to the 81-term multilinear coefficient tensor, store duplicated.
// ---------------------------------------------------------------------------

__device__ __forceinline__ void apply1q(float* vr, float* vi, int w,
    float g00r, float g00i, float g01r, float g01i,
    float g10r, float g10i, float g11r, float g11i)
{
    int m = 8 >> w;   // wire w lives at bit (3-w)
    #pragma unroll
    for (int z = 0; z < 16; z++) {
        if (z & m) continue;
        int z1 = z | m;
        float ar = vr[z],  ai = vi[z];
        float br = vr[z1], bi = vi[z1];
        vr[z]  = g00r*ar - g00i*ai + g01r*br - g01i*bi;
        vi[z]  = g00r*ai + g00i*ar + g01r*bi + g01i*br;
        vr[z1] = g10r*ar - g10i*ai + g11r*br - g11i*bi;
        vi[z1] = g10r*ai + g10i*ar + g11r*bi + g11i*br;
    }
}

__device__ __forceinline__ void applycnot(float* vr, float* vi, int c, int tg)
{
    int mc = 8 >> c, mt = 8 >> tg;
    #pragma unroll
    for (int z = 0; z < 16; z++) {
        if ((z & mc) && !(z & mt)) {
            int z1 = z | mt;
            float tr = vr[z], ti = vi[z];
            vr[z] = vr[z1]; vi[z] = vi[z1];
            vr[z1] = tr;    vi[z1] = ti;
        }
    }
}

__global__ void prep_kernel(const float* __restrict__ theta)
{
    __shared__ float Ur[16][16];
    __shared__ float Ui[16][16];
    __shared__ float A[4][16][16];
    int t = threadIdx.x;

    if (t < 16) {
        float vr[16], vi[16];
        #pragma unroll
        for (int z = 0; z < 16; z++) { vr[z] = 0.f; vi[z] = 0.f; }
        vr[t] = 1.f;

        float th0 = theta[0], th1 = theta[1], th2 = theta[2];
        float th3 = theta[3], th4 = theta[4], th5 = theta[5];

        { float c = cosf(0.5f*th0), s = sinf(0.5f*th0);
          apply1q(vr, vi, 0,  c,0.f, -s,0.f,  s,0.f,  c,0.f); }        // Ry w0
        { float c = cosf(0.5f*th1), s = sinf(0.5f*th1);
          apply1q(vr, vi, 1,  c,0.f, 0.f,-s, 0.f,-s,  c,0.f); }        // Rx w1
        { float c = cosf(0.5f*th2), s = sinf(0.5f*th2);
          apply1q(vr, vi, 2,  c,-s, 0.f,0.f, 0.f,0.f,  c,s); }         // Rz w2
        applycnot(vr, vi, 0, 1);
        { float c = cosf(0.5f*th3), s = sinf(0.5f*th3);
          apply1q(vr, vi, 3,  c,0.f, -s,0.f,  s,0.f,  c,0.f); }        // Ry w3
        applycnot(vr, vi, 2, 3);
        { float c = cosf(0.5f*th4), s = sinf(0.5f*th4);
          apply1q(vr, vi, 0,  c,0.f, 0.f,-s, 0.f,-s,  c,0.f); }        // Rx w0
        { float c = cosf(0.5f*th5), s = sinf(0.5f*th5);
          apply1q(vr, vi, 3,  c,-s, 0.f,0.f, 0.f,0.f,  c,s); }         // Rz w3

        #pragma unroll
        for (int z = 0; z < 16; z++) { Ur[z][t] = vr[z]; Ui[z][t] = vi[z]; }
    }
    __syncthreads();

    {
        int i = t >> 4, j = t & 15;
        float a0 = 0.f, a1 = 0.f, a2 = 0.f, a3 = 0.f;
        #pragma unroll
        for (int z = 0; z < 16; z++) {
            float re = Ur[z][i]*Ur[z][j] + Ui[z][i]*Ui[z][j];
            a0 += ((z >> 3) & 1) ? -re : re;
            a1 += ((z >> 2) & 1) ? -re : re;
            a2 += ((z >> 1) & 1) ? -re : re;
            a3 += ( z       & 1) ? -re : re;
        }
        A[0][i][j] = a0; A[1][i][j] = a1; A[2][i][j] = a2; A[3][i][j] = a3;
    }
    __syncthreads();

    if (t < 81) {
        int e = t;
        int ew[4];
        ew[0] = e / 27; ew[1] = (e / 9) % 3; ew[2] = (e / 3) % 3; ew[3] = e % 3;
        float c0 = 0.f, c1 = 0.f, c2 = 0.f, c3 = 0.f;
        for (int s = 0; s < 16; s++) {
            int i = 0, j = 0; float sg = 1.f;
            #pragma unroll
            for (int w = 0; w < 4; w++) {
                int bsel = (s >> w) & 1;
                int iw, jw; float ss;
                if (ew[w] == 0)      { iw = bsel; jw = bsel;     ss = 1.f; }
                else if (ew[w] == 1) { iw = bsel; jw = bsel;     ss = bsel ? -1.f : 1.f; }
                else                 { iw = bsel; jw = 1 - bsel; ss = 1.f; }
                i |= iw << (3 - w);
                j |= jw << (3 - w);
                sg *= ss;
            }
            c0 += sg * A[0][i][j];
            c1 += sg * A[1][i][j];
            c2 += sg * A[2][i][j];
            c3 += sg * A[3][i][j];
        }
        g_cd[e][0] = g_cd[e][1] = 0.0625f * c0;
        g_cd[e][2] = g_cd[e][3] = 0.0625f * c1;
        g_cd[e][4] = g_cd[e][5] = 0.0625f * c2;
        g_cd[e][6] = g_cd[e][7] = 0.0625f * c3;
    }
}

// ---------------------------------------------------------------------------
// Main fused kernel: one block = 4 images. 256 threads.
//   Phase 1: each thread evaluates up to 4 patches (one coeff stream feeds all 4,
//            SIMD2-packed into fp32x2 pairs) -> feats in smem
//   Phase 2: per-image 784x10 GEMV (64 threads/image) + log_softmax
// ---------------------------------------------------------------------------

__global__ __launch_bounds__(256, 2)
void quanv_kernel(const float* __restrict__ x,
                  const float* __restrict__ cw,
                  const float* __restrict__ W,
                  const float* __restrict__ bvec,
                  float* __restrict__ out)
{
    __shared__ __align__(16) float scd[81][8];
    __shared__ __align__(16) float feats[4][784];
    __shared__ float wpart[8][10];
    __shared__ float slog[4][10];

    int t = threadIdx.x;
    int b0 = blockIdx.x * 4;

    if (t < 162) ((float4*)scd)[t] = ((const float4*)g_cd)[t];
    float w00 = cw[0], w01 = cw[1], w10 = cw[2], w11 = cw[3];
    __syncthreads();

    // ---- Phase 1: angles for 4 patches ----
    float fC[4][4], fS[4][4];
    #pragma unroll
    for (int pp = 0; pp < 4; pp++) {
        int p = t + pp * 256;
        if (p < 784) {
            int img = p / 196, pi = p % 196;
            int r = pi / 7, c4 = pi % 7;
            const float* px = x + (size_t)(b0 + img) * 3136 + (2 * r) * 56 + 8 * c4;
            float4 r0a = *(const float4*)(px);
            float4 r0b = *(const float4*)(px + 4);
            float4 r1a = *(const float4*)(px + 56);
            float4 r1b = *(const float4*)(px + 60);
            float d0 = w00*r0a.x + w01*r0a.y + w10*r1a.x + w11*r1a.y;
            float d1 = w00*r0a.z + w01*r0a.w + w10*r1a.z + w11*r1a.w;
            float d2 = w00*r0b.x + w01*r0b.y + w10*r1b.x + w11*r1b.y;
            float d3 = w00*r0b.z + w01*r0b.w + w10*r1b.z + w11*r1b.w;
            __sincosf(d0, &fS[pp][0], &fC[pp][0]);
            __sincosf(d1, &fS[pp][1], &fC[pp][1]);
            __sincosf(d2, &fS[pp][2], &fC[pp][2]);
            __sincosf(d3, &fS[pp][3], &fC[pp][3]);
        } else {
            #pragma unroll
            for (int v = 0; v < 4; v++) { fC[pp][v] = 1.f; fS[pp][v] = 0.f; }
        }
    }

    // Pack patch pairs into fp32x2 lanes: pair pr holds patches (2pr, 2pr+1)
    F2 fc2[2][4], fs2[2][4];
    #pragma unroll
    for (int pr = 0; pr < 2; pr++)
        #pragma unroll
        for (int v = 0; v < 4; v++) {
            fc2[pr][v] = pack2(fC[2*pr][v], fC[2*pr+1][v]);
            fs2[pr][v] = pack2(fS[2*pr][v], fS[2*pr+1][v]);
        }

    const F2 ONE2 = 0x3f8000003f800000ULL;

    F2 m2[2][4];
    #pragma unroll
    for (int pr = 0; pr < 2; pr++)
        #pragma unroll
        for (int q = 0; q < 4; q++) m2[pr][q] = 0ULL;

    int idx = 0;
    #pragma unroll
    for (int e0 = 0; e0 < 3; e0++) {
        F2 pa2[2];
        #pragma unroll
        for (int pr = 0; pr < 2; pr++)
            pa2[pr] = (e0 == 0) ? ONE2 : (e0 == 1 ? fc2[pr][0] : fs2[pr][0]);
        #pragma unroll
        for (int e1 = 0; e1 < 3; e1++) {
            F2 pb2[2];
            #pragma unroll
            for (int pr = 0; pr < 2; pr++)
                pb2[pr] = (e1 == 0) ? pa2[pr]
                        : mul2(pa2[pr], (e1 == 1 ? fc2[pr][1] : fs2[pr][1]));
            #pragma unroll
            for (int e2 = 0; e2 < 3; e2++) {
                F2 pc2[2];
                #pragma unroll
                for (int pr = 0; pr < 2; pr++)
                    pc2[pr] = (e2 == 0) ? pb2[pr]
                            : mul2(pb2[pr], (e2 == 1 ? fc2[pr][2] : fs2[pr][2]));
                #pragma unroll
                for (int e3 = 0; e3 < 3; e3++) {
                    ulonglong2 k01 = *(const ulonglong2*)&scd[idx][0];
                    ulonglong2 k23 = *(const ulonglong2*)&scd[idx][4];
                    idx++;
                    #pragma unroll
                    for (int pr = 0; pr < 2; pr++) {
                        F2 pd2 = (e3 == 0) ? pc2[pr]
                               : mul2(pc2[pr], (e3 == 1 ? fc2[pr][3] : fs2[pr][3]));
                        m2[pr][0] = fma2(k01.x, pd2, m2[pr][0]);
                        m2[pr][1] = fma2(k01.y, pd2, m2[pr][1]);
                        m2[pr][2] = fma2(k23.x, pd2, m2[pr][2]);
                        m2[pr][3] = fma2(k23.y, pd2, m2[pr][3]);
                    }
                }
            }
        }
    }

    // Unpack + store feats
    #pragma unroll
    for (int pp = 0; pp < 4; pp++) {
        int p = t + pp * 256;
        if (p < 784) {
            int pr = pp >> 1;
            float v0, v1, v2, v3, hx;
            if ((pp & 1) == 0) {
                unpack2(m2[pr][0], v0, hx);
                unpack2(m2[pr][1], v1, hx);
                unpack2(m2[pr][2], v2, hx);
                unpack2(m2[pr][3], v3, hx);
            } else {
                unpack2(m2[pr][0], hx, v0);
                unpack2(m2[pr][1], hx, v1);
                unpack2(m2[pr][2], hx, v2);
                unpack2(m2[pr][3], hx, v3);
            }
            int img = p / 196, pi = p % 196;
            *(float4*)&feats[img][4 * pi] = make_float4(v0, v1, v2, v3);
        }
    }
    __syncthreads();

    // ---- Phase 2: GEMV (64 threads per image) + log_softmax ----
    int img = t >> 6;
    int tp = t & 63;
    float acc[10];
    #pragma unroll
    for (int k = 0; k < 10; k++) acc[k] = 0.f;
    for (int f = tp; f < 784; f += 64) {
        float v = feats[img][f];
        #pragma unroll
        for (int k = 0; k < 10; k++)
            acc[k] = fmaf(v, __ldg(&W[k * 784 + f]), acc[k]);
    }
    #pragma unroll
    for (int k = 0; k < 10; k++) {
        float v = acc[k];
        v += __shfl_xor_sync(0xffffffffu, v, 16);
        v += __shfl_xor_sync(0xffffffffu, v, 8);
        v += __shfl_xor_sync(0xffffffffu, v, 4);
        v += __shfl_xor_sync(0xffffffffu, v, 2);
        v += __shfl_xor_sync(0xffffffffu, v, 1);
        acc[k] = v;
    }
    int lane = t & 31, wid = t >> 5;
    if (lane == 0) {
        #pragma unroll
        for (int k = 0; k < 10; k++) wpart[wid][k] = acc[k];
    }
    __syncthreads();
    if (t < 40) {
        int i = t / 10, k = t % 10;
        slog[i][k] = bvec[k] + wpart[2 * i][k] + wpart[2 * i + 1][k];
    }
    __syncthreads();
    if (t < 4) {
        float mx = slog[t][0];
        #pragma unroll
        for (int k = 1; k < 10; k++) mx = fmaxf(mx, slog[t][k]);
        float se = 0.f;
        #pragma unroll
        for (int k = 0; k < 10; k++) se += __expf(slog[t][k] - mx);
        float l = mx + __logf(se);
        #pragma unroll
        for (int k = 0; k < 10; k++)
            out[(size_t)(b0 + t) * 10 + k] = slog[t][k] - l;
    }
}

// ---------------------------------------------------------------------------

extern "C" void kernel_launch(void* const* d_in, const int* in_sizes, int n_in,
                              void* d_out, int out_size)
{
    const float* x     = (const float*)d_in[0];   // [2048,1,56,56]
    const float* cw    = (const float*)d_in[1];   // [1,1,2,2]
    const float* theta = (const float*)d_in[2];   // [6]
    const float* W     = (const float*)d_in[3];   // [10,784]
    const float* bvec  = (const float*)d_in[4];   // [10]
    float* out = (float*)d_out;                   // [2048,10]

    int B = in_sizes[0] / 3136;                   // 2048

    prep_kernel<<<1, 256>>>(theta);
    quanv_kernel<<<B / 4, 256>>>(x, cw, W, bvec, out);
}

// round 7
// speedup vs baseline: 1.4267x; 1.3050x over previous
#include <cuda_runtime.h>
#include <math.h>

// ---------------------------------------------------------------------------
// Fully fused kernel. The circuit factorizes: all entangling gates stay within
// wire pairs {0,1} and {2,3}, so U = U_A (x) U_B and each PauliZ expectation
// is a 9-term bilinear form over (1, cos d, sin d) of just two angles.
// Every block redundantly computes the tiny theta-dependent prep (~2 warps of
// work), then evaluates 196 patches + GEMV + log_softmax for one image.
// ---------------------------------------------------------------------------

__device__ __forceinline__ void ap1(float* vr, float* vi, int m,
    float g00r, float g00i, float g01r, float g01i,
    float g10r, float g10i, float g11r, float g11i)
{
    #pragma unroll
    for (int z = 0; z < 4; z++) {
        if (z & m) continue;
        int z1 = z | m;
        float ar = vr[z],  ai = vi[z];
        float br = vr[z1], bi = vi[z1];
        vr[z]  = g00r*ar - g00i*ai + g01r*br - g01i*bi;
        vi[z]  = g00r*ai + g00i*ar + g01r*bi + g01i*br;
        vr[z1] = g10r*ar - g10i*ai + g11r*br - g11i*bi;
        vi[z1] = g10r*ai + g10i*ar + g11r*bi + g11i*br;
    }
}

__global__ __launch_bounds__(256)
void fused_kernel(const float* __restrict__ x,
                  const float* __restrict__ cw,
                  const float* __restrict__ theta,
                  const float* __restrict__ W,
                  const float* __restrict__ bvec,
                  float* __restrict__ out)
{
    __shared__ float Ur[2][4][4], Ui[2][4][4];     // [pair][z][col]
    __shared__ float M[2][2][4][4];                // [pair][q][i][j]
    __shared__ float2 scA[9], scB[9];              // 9-term coeffs per pair
    __shared__ __align__(16) float feats[784];
    __shared__ float wpart[8][10];
    __shared__ float slog[10];

    int t = threadIdx.x;
    int b = blockIdx.x;

    // ---- Prep stage 1: columns of U_A (wires 0,1) and U_B (wires 2,3) ----
    // local bit1 = first wire of pair, bit0 = second wire.
    if (t < 8) {
        int pair = t >> 2;
        int col  = t & 3;
        float vr[4] = {0.f, 0.f, 0.f, 0.f};
        float vi[4] = {0.f, 0.f, 0.f, 0.f};
        vr[col] = 1.f;
        if (pair == 0) {
            // order: Ry(th0) w0, Rx(th1) w1, CNOT(0,1), Rx(th4) w0
            { float c = cosf(0.5f*theta[0]), s = sinf(0.5f*theta[0]);
              ap1(vr, vi, 2,  c,0.f, -s,0.f,  s,0.f,  c,0.f); }
            { float c = cosf(0.5f*theta[1]), s = sinf(0.5f*theta[1]);
              ap1(vr, vi, 1,  c,0.f, 0.f,-s, 0.f,-s,  c,0.f); }
            // CNOT: ctrl bit1, tgt bit0
            { float tr = vr[2], ti = vi[2];
              vr[2] = vr[3]; vi[2] = vi[3]; vr[3] = tr; vi[3] = ti; }
            { float c = cosf(0.5f*theta[4]), s = sinf(0.5f*theta[4]);
              ap1(vr, vi, 2,  c,0.f, 0.f,-s, 0.f,-s,  c,0.f); }
        } else {
            // order: Rz(th2) w2, Ry(th3) w3, CNOT(2,3), Rz(th5) w3
            { float c = cosf(0.5f*theta[2]), s = sinf(0.5f*theta[2]);
              ap1(vr, vi, 2,  c,-s, 0.f,0.f, 0.f,0.f,  c,s); }
            { float c = cosf(0.5f*theta[3]), s = sinf(0.5f*theta[3]);
              ap1(vr, vi, 1,  c,0.f, -s,0.f,  s,0.f,  c,0.f); }
            { float tr = vr[2], ti = vi[2];
              vr[2] = vr[3]; vi[2] = vi[3]; vr[3] = tr; vi[3] = ti; }
            { float c = cosf(0.5f*theta[5]), s = sinf(0.5f*theta[5]);
              ap1(vr, vi, 1,  c,-s, 0.f,0.f, 0.f,0.f,  c,s); }
        }
        #pragma unroll
        for (int z = 0; z < 4; z++) { Ur[pair][z][col] = vr[z]; Ui[pair][z][col] = vi[z]; }
    }
    __syncthreads();

    // ---- Prep stage 2: M[pair][q][i][j] = sum_z sign_q(z) Re(conj(U[z][i]) U[z][j]) ----
    if (t < 32) {
        int pair = t >> 4;
        int i = (t >> 2) & 3, j = t & 3;
        float a0 = 0.f, a1 = 0.f;
        #pragma unroll
        for (int z = 0; z < 4; z++) {
            float re = Ur[pair][z][i]*Ur[pair][z][j] + Ui[pair][z][i]*Ui[pair][z][j];
            a0 += (z & 2) ? -re : re;   // first wire of pair: bit1
            a1 += (z & 1) ? -re : re;   // second wire: bit0
        }
        M[pair][0][i][j] = a0;
        M[pair][1][i][j] = a1;
    }
    __syncthreads();

    // ---- Prep stage 3: collapse to 9-term coefficients per pair ----
    if (t < 18) {
        int pair = (t >= 9) ? 1 : 0;
        int e = pair ? (t - 9) : t;
        int e0 = e / 3, e1 = e % 3;
        float c0 = 0.f, c1 = 0.f;
        #pragma unroll
        for (int s = 0; s < 4; s++) {
            int i = 0, j = 0; float sg = 1.f;
            // wire local0 -> bit1, basis index e0
            { int bsel = s & 1; int iw, jw; float ss;
              if (e0 == 0)      { iw = bsel; jw = bsel;     ss = 1.f; }
              else if (e0 == 1) { iw = bsel; jw = bsel;     ss = bsel ? -1.f : 1.f; }
              else              { iw = bsel; jw = 1 - bsel; ss = 1.f; }
              i |= iw << 1; j |= jw << 1; sg *= ss; }
            // wire local1 -> bit0, basis index e1
            { int bsel = (s >> 1) & 1; int iw, jw; float ss;
              if (e1 == 0)      { iw = bsel; jw = bsel;     ss = 1.f; }
              else if (e1 == 1) { iw = bsel; jw = bsel;     ss = bsel ? -1.f : 1.f; }
              else              { iw = bsel; jw = 1 - bsel; ss = 1.f; }
              i |= iw; j |= jw; sg *= ss; }
            c0 += sg * M[pair][0][i][j];
            c1 += sg * M[pair][1][i][j];
        }
        float2 v = make_float2(0.25f * c0, 0.25f * c1);
        if (pair == 0) scA[e] = v; else scB[e] = v;
    }
    float w00 = cw[0], w01 = cw[1], w10 = cw[2], w11 = cw[3];
    __syncthreads();

    // ---- Phase 1: 196 patches -> features ----
    if (t < 196) {
        int r  = t / 7;
        int c4 = t % 7;
        const float* px = x + (size_t)b * 3136 + (2 * r) * 56 + 8 * c4;
        float4 r0a = *(const float4*)(px);
        float4 r0b = *(const float4*)(px + 4);
        float4 r1a = *(const float4*)(px + 56);
        float4 r1b = *(const float4*)(px + 60);

        float d0 = w00*r0a.x + w01*r0a.y + w10*r1a.x + w11*r1a.y;
        float d1 = w00*r0a.z + w01*r0a.w + w10*r1a.z + w11*r1a.w;
        float d2 = w00*r0b.x + w01*r0b.y + w10*r1b.x + w11*r1b.y;
        float d3 = w00*r0b.z + w01*r0b.w + w10*r1b.z + w11*r1b.w;

        float s0, c0, s1, c1, s2, c2, s3, c3;
        __sincosf(d0, &s0, &c0);
        __sincosf(d1, &s1, &c1);
        __sincosf(d2, &s2, &c2);
        __sincosf(d3, &s3, &c3);

        float fa[3] = {1.f, c0, s0};
        float fb[3] = {1.f, c1, s1};
        float fc[3] = {1.f, c2, s2};
        float fd[3] = {1.f, c3, s3};

        float m0 = 0.f, m1 = 0.f, m2 = 0.f, m3 = 0.f;
        int idx = 0;
        #pragma unroll
        for (int e0 = 0; e0 < 3; e0++) {
            #pragma unroll
            for (int e1 = 0; e1 < 3; e1++) {
                float pA = fa[e0] * fb[e1];
                float pB = fc[e0] * fd[e1];
                float2 kA = scA[idx];
                float2 kB = scB[idx];
                idx++;
                m0 = fmaf(kA.x, pA, m0);
                m1 = fmaf(kA.y, pA, m1);
                m2 = fmaf(kB.x, pB, m2);
                m3 = fmaf(kB.y, pB, m3);
            }
        }
        *(float4*)(&feats[4 * t]) = make_float4(m0, m1, m2, m3);
    }
    __syncthreads();

    // ---- Phase 2: 784x10 GEMV + log_softmax ----
    float acc[10];
    #pragma unroll
    for (int k = 0; k < 10; k++) acc[k] = 0.f;
    for (int f = t; f < 784; f += 256) {
        float v = feats[f];
        #pragma unroll
        for (int k = 0; k < 10; k++)
            acc[k] = fmaf(v, __ldg(&W[k * 784 + f]), acc[k]);
    }
    #pragma unroll
    for (int k = 0; k < 10; k++) {
        float v = acc[k];
        v += __shfl_xor_sync(0xffffffffu, v, 16);
        v += __shfl_xor_sync(0xffffffffu, v, 8);
        v += __shfl_xor_sync(0xffffffffu, v, 4);
        v += __shfl_xor_sync(0xffffffffu, v, 2);
        v += __shfl_xor_sync(0xffffffffu, v, 1);
        acc[k] = v;
    }
    int lane = t & 31, wid = t >> 5;
    if (lane == 0) {
        #pragma unroll
        for (int k = 0; k < 10; k++) wpart[wid][k] = acc[k];
    }
    __syncthreads();
    if (t < 10) {
        float v = bvec[t];
        #pragma unroll
        for (int w = 0; w < 8; w++) v += wpart[w][t];
        slog[t] = v;
    }
    __syncthreads();
    if (t == 0) {
        float mx = slog[0];
        #pragma unroll
        for (int k = 1; k < 10; k++) mx = fmaxf(mx, slog[k]);
        float se = 0.f;
        #pragma unroll
        for (int k = 0; k < 10; k++) se += __expf(slog[k] - mx);
        float l = mx + __logf(se);
        #pragma unroll
        for (int k = 0; k < 10; k++) out[(size_t)b * 10 + k] = slog[k] - l;
    }
}

// ---------------------------------------------------------------------------

extern "C" void kernel_launch(void* const* d_in, const int* in_sizes, int n_in,
                              void* d_out, int out_size)
{
    const float* x     = (const float*)d_in[0];   // [2048,1,56,56]
    const float* cw    = (const float*)d_in[1];   // [1,1,2,2]
    const float* theta = (const float*)d_in[2];   // [6]
    const float* W     = (const float*)d_in[3];   // [10,784]
    const float* bvec  = (const float*)d_in[4];   // [10]
    float* out = (float*)d_out;                   // [2048,10]

    int B = in_sizes[0] / 3136;                   // 2048

    fused_kernel<<<B, 256>>>(x, cw, theta, W, bvec, out);
}